// round 14
// baseline (speedup 1.0000x reference)
#include <cuda_runtime.h>
#include <cuda_bf16.h>
#include <stdint.h>

// Scratch (no cudaMalloc allowed).
#define MAX_NODES 131072
__device__ unsigned char g_tbl4[MAX_NODES / 2];  // nibble-packed classes
__device__ double g_sum;
__device__ unsigned int g_count;

// ---------------------------------------------------------------------------
// Kernel 1: nibble-pack classes (2 nodes/thread); reset accumulator + counter.
// ---------------------------------------------------------------------------
__global__ void pack_kernel(const int* __restrict__ node_classes, int n_nodes) {
    int q = blockIdx.x * blockDim.x + threadIdx.x;
    if (q == 0) { g_sum = 0.0; g_count = 0u; }

    int base = q * 2;
    if (base + 2 <= n_nodes) {
        int2 c = *(const int2*)(node_classes + base);
        g_tbl4[q] = (unsigned char)((c.x & 15) | ((c.y & 15) << 4));
    } else if (base < n_nodes) {
        g_tbl4[q] = (unsigned char)(node_classes[base] & 15);
    }
}

// ---------------------------------------------------------------------------
// Kernel 2: main edge loop + fused finalize. 1 CTA/SM, 1024 threads.
//   dyn smem: [0, ceil(n_nodes/2)) nibble table, then (128B aligned)
//             C*32 uint bank-replicated adjacency masks.  (~51.5KB total ->
//             L1D carveout ~176KB for the streaming loads.)
// ---------------------------------------------------------------------------
__global__ void __launch_bounds__(1024, 1)
edge_loss_kernel(const float* __restrict__ edge_scores,
                 const int* __restrict__ edge_indices,
                 const float* __restrict__ adj,
                 float* __restrict__ out,
                 int n_edges, int n_nodes, int C) {
    extern __shared__ unsigned char smem[];
    unsigned char* s_tbl4 = smem;
    int tbl_bytes = (n_nodes + 1) >> 1;
    int mask_off = (tbl_bytes + 127) & ~127;
    unsigned int* s_mask = (unsigned int*)(smem + mask_off);

    int tid = threadIdx.x;
    int nthreads = blockDim.x;
    int lane = tid & 31;

    // Stage nibble table (~50KB) into shared.
    {
        int n16 = tbl_bytes >> 4;
        const uint4* s16 = (const uint4*)g_tbl4;
        uint4* d16 = (uint4*)s_tbl4;
        for (int i = tid; i < n16; i += nthreads) d16[i] = s16[i];
        for (int i = (n16 << 4) + tid; i < tbl_bytes; i += nthreads)
            s_tbl4[i] = g_tbl4[i];
    }
    // Bank-replicated adjacency masks: s_mask[cls*32 + lane] == mask[cls].
    if (tid < C * 32) {
        int cls = tid >> 5;
        unsigned int m = 0;
        for (int j = 0; j < C; j++)
            m |= (adj[cls * C + j] != 0.0f ? 1u : 0u) << j;
        s_mask[tid] = m;
    }
    __syncthreads();

    const int* src_idx = edge_indices;            // row 0
    const int* dst_idx = edge_indices + n_edges;  // row 1

    int nq = n_edges >> 2;  // groups of 4 edges per thread-iter
    int gtid = blockIdx.x * nthreads + tid;
    int gstride = gridDim.x * nthreads;
    int guard = n_nodes - 1;
    const float LN2 = 0.6931471805599453f;

    float acc = 0.0f;

    #pragma unroll 2
    for (int q = gtid; q < nq; q += gstride) {
        int4 s4 = *(const int4*)(src_idx + 4 * q);
        int4 d4 = *(const int4*)(dst_idx + 4 * q);
        float4 sc = *(const float4*)(edge_scores + 4 * q);

        int ia0 = min(s4.x, guard), ib0 = min(d4.x, guard);
        int ia1 = min(s4.y, guard), ib1 = min(d4.y, guard);
        int ia2 = min(s4.z, guard), ib2 = min(d4.z, guard);
        int ia3 = min(s4.w, guard), ib3 = min(d4.w, guard);

        unsigned a0 = (s_tbl4[ia0 >> 1] >> ((ia0 & 1) << 2)) & 15u;
        unsigned b0 = (s_tbl4[ib0 >> 1] >> ((ib0 & 1) << 2)) & 15u;
        unsigned a1 = (s_tbl4[ia1 >> 1] >> ((ia1 & 1) << 2)) & 15u;
        unsigned b1 = (s_tbl4[ib1 >> 1] >> ((ib1 & 1) << 2)) & 15u;
        unsigned a2 = (s_tbl4[ia2 >> 1] >> ((ia2 & 1) << 2)) & 15u;
        unsigned b2 = (s_tbl4[ib2 >> 1] >> ((ib2 & 1) << 2)) & 15u;
        unsigned a3 = (s_tbl4[ia3 >> 1] >> ((ia3 & 1) << 2)) & 15u;
        unsigned b3 = (s_tbl4[ib3 >> 1] >> ((ib3 & 1) << 2)) & 15u;

        unsigned y0 = (s_mask[(a0 << 5) | lane] >> b0) & 1u;
        unsigned y1 = (s_mask[(a1 << 5) | lane] >> b1) & 1u;
        unsigned y2 = (s_mask[(a2 << 5) | lane] >> b2) & 1u;
        unsigned y3 = (s_mask[(a3 << 5) | lane] >> b3) & 1u;

        float s0 = sc.x, s1 = sc.y, s2 = sc.z, s3 = sc.w;
        // per_edge = max(s,0) - s*y + log(1 + exp(-|s|))
        float e0 = __expf(-fabsf(s0));
        float e1 = __expf(-fabsf(s1));
        float e2 = __expf(-fabsf(s2));
        float e3 = __expf(-fabsf(s3));
        acc += fmaxf(s0, 0.0f) - (y0 ? s0 : 0.0f) + LN2 * __log2f(1.0f + e0);
        acc += fmaxf(s1, 0.0f) - (y1 ? s1 : 0.0f) + LN2 * __log2f(1.0f + e1);
        acc += fmaxf(s2, 0.0f) - (y2 ? s2 : 0.0f) + LN2 * __log2f(1.0f + e2);
        acc += fmaxf(s3, 0.0f) - (y3 ? s3 : 0.0f) + LN2 * __log2f(1.0f + e3);
    }

    // Tail edges (n_edges % 4).
    if (gtid == 0) {
        for (int e = nq << 2; e < n_edges; e++) {
            int ia = min(src_idx[e], guard);
            int ib = min(dst_idx[e], guard);
            unsigned a = (s_tbl4[ia >> 1] >> ((ia & 1) << 2)) & 15u;
            unsigned b = (s_tbl4[ib >> 1] >> ((ib & 1) << 2)) & 15u;
            unsigned y = (s_mask[(a << 5) | lane] >> b) & 1u;
            float s = edge_scores[e];
            acc += fmaxf(s, 0.0f) - (y ? s : 0.0f) +
                   LN2 * __log2f(1.0f + __expf(-fabsf(s)));
        }
    }

    // Block reduction: warp shuffle -> shared -> one double atomic per block.
    __shared__ float red[32];
    int wid = tid >> 5;
    #pragma unroll
    for (int off = 16; off > 0; off >>= 1)
        acc += __shfl_xor_sync(0xFFFFFFFFu, acc, off);
    if (lane == 0) red[wid] = acc;
    __syncthreads();
    if (wid == 0) {
        int nw = nthreads >> 5;
        float v = (lane < nw) ? red[lane] : 0.0f;
        #pragma unroll
        for (int off = 16; off > 0; off >>= 1)
            v += __shfl_xor_sync(0xFFFFFFFFu, v, off);
        if (lane == 0) {
            atomicAdd(&g_sum, (double)v);
            __threadfence();
            unsigned done = atomicAdd(&g_count, 1u);
            if (done == gridDim.x - 1) {
                double total = *((volatile double*)&g_sum);
                out[0] = (float)(total / (double)n_edges);
            }
        }
    }
}

extern "C" void kernel_launch(void* const* d_in, const int* in_sizes, int n_in,
                              void* d_out, int out_size) {
    // Inputs: node_classes(int32), edge_scores(f32), edge_indices(int32, 2xN),
    // valid_adjacency(f32, CxC).
    const int* node_classes = (const int*)d_in[0];
    const float* edge_scores = (const float*)d_in[1];
    const int* edge_indices = (const int*)d_in[2];
    const float* adj = (const float*)d_in[3];

    int n_nodes = in_sizes[0];
    int n_edges = in_sizes[1];
    int C = 1;
    while (C * C < in_sizes[3]) C++;  // 144 -> 12

    int tbl_bytes = (n_nodes + 1) >> 1;
    int mask_off = (tbl_bytes + 127) & ~127;
    size_t smem_bytes = (size_t)mask_off + (size_t)C * 32 * sizeof(unsigned int);

    cudaFuncSetAttribute(edge_loss_kernel,
                         cudaFuncAttributeMaxDynamicSharedMemorySize,
                         (int)smem_bytes);

    int nsm = 148;
    cudaDeviceGetAttribute(&nsm, cudaDevAttrMultiProcessorCount, 0);

    int pack_threads = 256;
    int pack_blocks = (((n_nodes + 1) / 2) + pack_threads - 1) / pack_threads;
    pack_kernel<<<pack_blocks, pack_threads>>>(node_classes, n_nodes);

    // 1 CTA per SM (smem ~51.5KB) -> maximal L1D carveout, halved staging.
    edge_loss_kernel<<<nsm, 1024, smem_bytes>>>(edge_scores, edge_indices,
                                                adj, (float*)d_out,
                                                n_edges, n_nodes, C);
}

// round 17
// speedup vs baseline: 1.0580x; 1.0580x over previous
#include <cuda_runtime.h>
#include <cuda_bf16.h>
#include <stdint.h>

// Scratch (no cudaMalloc allowed).
#define MAX_NODES 131072
__device__ unsigned char g_tbl4[MAX_NODES / 2];  // nibble-packed classes
__device__ double g_sum;
__device__ unsigned int g_count;

// ---------------------------------------------------------------------------
// Kernel 1: nibble-pack classes (2 nodes/thread); reset accumulator + counter.
// ---------------------------------------------------------------------------
__global__ void pack_kernel(const int* __restrict__ node_classes, int n_nodes) {
    int q = blockIdx.x * blockDim.x + threadIdx.x;
    if (q == 0) { g_sum = 0.0; g_count = 0u; }

    int base = q * 2;
    if (base + 2 <= n_nodes) {
        int2 c = *(const int2*)(node_classes + base);
        g_tbl4[q] = (unsigned char)((c.x & 15) | ((c.y & 15) << 4));
    } else if (base < n_nodes) {
        g_tbl4[q] = (unsigned char)(node_classes[base] & 15);
    }
}

// ---------------------------------------------------------------------------
// Kernel 2: main edge loop + fused finalize. 2 CTAs/SM x 1024 = 64 warps/SM.
//   dyn smem: [0, ceil(n_nodes/2)) nibble table, then (128B aligned)
//             C*32 uint bank-replicated adjacency masks (~51.5KB/CTA).
// ---------------------------------------------------------------------------
__global__ void __launch_bounds__(1024, 2)
edge_loss_kernel(const float* __restrict__ edge_scores,
                 const int* __restrict__ edge_indices,
                 const float* __restrict__ adj,
                 float* __restrict__ out,
                 int n_edges, int n_nodes, int C) {
    extern __shared__ unsigned char smem[];
    unsigned char* s_tbl4 = smem;
    int tbl_bytes = (n_nodes + 1) >> 1;
    int mask_off = (tbl_bytes + 127) & ~127;
    unsigned int* s_mask = (unsigned int*)(smem + mask_off);

    int tid = threadIdx.x;
    int nthreads = blockDim.x;
    int lane = tid & 31;

    // Stage nibble table (~50KB) into shared.
    {
        int n16 = tbl_bytes >> 4;
        const uint4* s16 = (const uint4*)g_tbl4;
        uint4* d16 = (uint4*)s_tbl4;
        for (int i = tid; i < n16; i += nthreads) d16[i] = s16[i];
        for (int i = (n16 << 4) + tid; i < tbl_bytes; i += nthreads)
            s_tbl4[i] = g_tbl4[i];
    }
    // Bank-replicated adjacency masks: s_mask[cls*32 + lane] == mask[cls].
    if (tid < C * 32) {
        int cls = tid >> 5;
        unsigned int m = 0;
        for (int j = 0; j < C; j++)
            m |= (adj[cls * C + j] != 0.0f ? 1u : 0u) << j;
        s_mask[tid] = m;
    }
    __syncthreads();

    const int* src_idx = edge_indices;            // row 0
    const int* dst_idx = edge_indices + n_edges;  // row 1

    int nq = n_edges >> 2;  // groups of 4 edges per thread-iter
    int gtid = blockIdx.x * nthreads + tid;
    int gstride = gridDim.x * nthreads;
    const float LN2 = 0.6931471805599453f;

    float acc = 0.0f;

    for (int q = gtid; q < nq; q += gstride) {
        int4 s4 = *(const int4*)(src_idx + 4 * q);
        int4 d4 = *(const int4*)(dst_idx + 4 * q);
        float4 sc = *(const float4*)(edge_scores + 4 * q);

        // Indices are in [0, n_nodes) by construction (reference randint).
        unsigned a0 = (s_tbl4[s4.x >> 1] >> ((s4.x & 1) << 2)) & 15u;
        unsigned b0 = (s_tbl4[d4.x >> 1] >> ((d4.x & 1) << 2)) & 15u;
        unsigned a1 = (s_tbl4[s4.y >> 1] >> ((s4.y & 1) << 2)) & 15u;
        unsigned b1 = (s_tbl4[d4.y >> 1] >> ((d4.y & 1) << 2)) & 15u;
        unsigned a2 = (s_tbl4[s4.z >> 1] >> ((s4.z & 1) << 2)) & 15u;
        unsigned b2 = (s_tbl4[d4.z >> 1] >> ((d4.z & 1) << 2)) & 15u;
        unsigned a3 = (s_tbl4[s4.w >> 1] >> ((s4.w & 1) << 2)) & 15u;
        unsigned b3 = (s_tbl4[d4.w >> 1] >> ((d4.w & 1) << 2)) & 15u;

        unsigned y0 = (s_mask[(a0 << 5) | lane] >> b0) & 1u;
        unsigned y1 = (s_mask[(a1 << 5) | lane] >> b1) & 1u;
        unsigned y2 = (s_mask[(a2 << 5) | lane] >> b2) & 1u;
        unsigned y3 = (s_mask[(a3 << 5) | lane] >> b3) & 1u;

        float s0 = sc.x, s1 = sc.y, s2 = sc.z, s3 = sc.w;
        // per_edge = max(s,0) - s*y + log(1 + exp(-|s|))
        float e0 = __expf(-fabsf(s0));
        float e1 = __expf(-fabsf(s1));
        float e2 = __expf(-fabsf(s2));
        float e3 = __expf(-fabsf(s3));
        acc += fmaxf(s0, 0.0f) - (y0 ? s0 : 0.0f) + LN2 * __log2f(1.0f + e0);
        acc += fmaxf(s1, 0.0f) - (y1 ? s1 : 0.0f) + LN2 * __log2f(1.0f + e1);
        acc += fmaxf(s2, 0.0f) - (y2 ? s2 : 0.0f) + LN2 * __log2f(1.0f + e2);
        acc += fmaxf(s3, 0.0f) - (y3 ? s3 : 0.0f) + LN2 * __log2f(1.0f + e3);
    }

    // Tail edges (n_edges % 4).
    if (gtid == 0) {
        for (int e = nq << 2; e < n_edges; e++) {
            int ia = src_idx[e];
            int ib = dst_idx[e];
            unsigned a = (s_tbl4[ia >> 1] >> ((ia & 1) << 2)) & 15u;
            unsigned b = (s_tbl4[ib >> 1] >> ((ib & 1) << 2)) & 15u;
            unsigned y = (s_mask[(a << 5) | lane] >> b) & 1u;
            float s = edge_scores[e];
            acc += fmaxf(s, 0.0f) - (y ? s : 0.0f) +
                   LN2 * __log2f(1.0f + __expf(-fabsf(s)));
        }
    }

    // Block reduction: warp shuffle -> shared -> one double atomic per block.
    __shared__ float red[32];
    int wid = tid >> 5;
    #pragma unroll
    for (int off = 16; off > 0; off >>= 1)
        acc += __shfl_xor_sync(0xFFFFFFFFu, acc, off);
    if (lane == 0) red[wid] = acc;
    __syncthreads();
    if (wid == 0) {
        int nw = nthreads >> 5;
        float v = (lane < nw) ? red[lane] : 0.0f;
        #pragma unroll
        for (int off = 16; off > 0; off >>= 1)
            v += __shfl_xor_sync(0xFFFFFFFFu, v, off);
        if (lane == 0) {
            atomicAdd(&g_sum, (double)v);
            __threadfence();
            unsigned done = atomicAdd(&g_count, 1u);
            if (done == gridDim.x - 1) {
                double total = *((volatile double*)&g_sum);
                out[0] = (float)(total / (double)n_edges);
            }
        }
    }
}

extern "C" void kernel_launch(void* const* d_in, const int* in_sizes, int n_in,
                              void* d_out, int out_size) {
    // Inputs: node_classes(int32), edge_scores(f32), edge_indices(int32, 2xN),
    // valid_adjacency(f32, CxC).
    const int* node_classes = (const int*)d_in[0];
    const float* edge_scores = (const float*)d_in[1];
    const int* edge_indices = (const int*)d_in[2];
    const float* adj = (const float*)d_in[3];

    int n_nodes = in_sizes[0];
    int n_edges = in_sizes[1];
    int C = 1;
    while (C * C < in_sizes[3]) C++;  // 144 -> 12

    int tbl_bytes = (n_nodes + 1) >> 1;
    int mask_off = (tbl_bytes + 127) & ~127;
    size_t smem_bytes = (size_t)mask_off + (size_t)C * 32 * sizeof(unsigned int);

    cudaFuncSetAttribute(edge_loss_kernel,
                         cudaFuncAttributeMaxDynamicSharedMemorySize,
                         (int)smem_bytes);

    int nsm = 148;
    cudaDeviceGetAttribute(&nsm, cudaDevAttrMultiProcessorCount, 0);

    int pack_threads = 256;
    int pack_blocks = (((n_nodes + 1) / 2) + pack_threads - 1) / pack_threads;
    pack_kernel<<<pack_blocks, pack_threads>>>(node_classes, n_nodes);

    // 2 CTAs per SM x 1024 threads = 64 warps/SM, smem ~51.5KB/CTA.
    edge_loss_kernel<<<2 * nsm, 1024, smem_bytes>>>(edge_scores, edge_indices,
                                                    adj, (float*)d_out,
                                                    n_edges, n_nodes, C);
}